// round 5
// baseline (speedup 1.0000x reference)
#include <cuda_runtime.h>

#define T_STEPS 16384
#define H 361

#define SEG 48
#define SEGP 52
#define NSEG 8
#define HP (NSEG * SEGP)   /* 416 */
#define RPC 46
#define CSZ 8
#define TXBYTES 1448       /* 181 x 8B pair-messages per consumer per step */

#define KAPPA_F 32.84045313f
#define NORMF   2.2773755f
#define DEG2RAD 0.017453292519943295f

// ---------------- device scratch ----------------
__device__ float g_xw[T_STEPS * H];
__device__ float g_W2T[H * 368];
__device__ float g_A[H];
__device__ float g_C[H];
__device__ float g_hs[T_STEPS * H];

__device__ __forceinline__ unsigned smem_u32(const void* p) {
    return (unsigned)__cvta_generic_to_shared(p);
}
__device__ __forceinline__ unsigned mapa_u32(unsigned addr, unsigned rank) {
    unsigned r;
    asm("mapa.shared::cluster.u32 %0, %1, %2;" : "=r"(r) : "r"(addr), "r"(rank));
    return r;
}

// ---------------- K0: collapse rule projection + biases ----------------
__global__ void k0_prep(const float* __restrict__ w_rule, const float* __restrict__ b_rule,
                        const float* __restrict__ w_ih, const float* __restrict__ b_ih,
                        const float* __restrict__ b_hh) {
    int j = blockIdx.x * blockDim.x + threadIdx.x;
    if (j >= H) return;
    float a = 0.f, c = 0.f;
    const float* wr = w_ih + j * 489;
    for (int k = 0; k < 128; k++) {
        float w = wr[k];
        a = fmaf(w_rule[k], w, a);
        c = fmaf(b_rule[k], w, c);
    }
    g_A[j] = a;
    g_C[j] = c + b_ih[j] + b_hh[j];
}

__global__ void k0_transpose(const float* __restrict__ w_ih) {
    int idx = blockIdx.x * blockDim.x + threadIdx.x;
    if (idx >= H * H) return;
    int j = idx / H;
    int g = idx - j * H;
    g_W2T[g * 368 + j] = w_ih[j * 489 + 128 + g];
}

// ---------------- K1: xw precompute ----------------
#define TT 16
__global__ __launch_bounds__(384) void k1_xw(const float* __restrict__ angle,
                                             const float* __restrict__ rule) {
    __shared__ float sE[TT][H];
    __shared__ float sAng[TT], sRule[TT];
    int tid = threadIdx.x;
    int t0 = blockIdx.x * TT;
    if (tid < TT) {
        sAng[tid]  = angle[t0 + tid] * DEG2RAD;
        sRule[tid] = rule[t0 + tid];
    }
    __syncthreads();
    if (tid < H) {
        float gr = (float)tid * DEG2RAD;
        #pragma unroll
        for (int tt = 0; tt < TT; tt++) {
            float th = gr - sAng[tt];
            sE[tt][tid] = __expf(KAPPA_F * (cosf(th) - 1.0f)) * NORMF;
        }
    }
    __syncthreads();
    if (tid < H) {
        float acc[TT];
        #pragma unroll
        for (int tt = 0; tt < TT; tt++) acc[tt] = 0.f;
        #pragma unroll 2
        for (int g = 0; g < H; g++) {
            float w = g_W2T[g * 368 + tid];
            #pragma unroll
            for (int tt = 0; tt < TT; tt++) acc[tt] = fmaf(sE[tt][g], w, acc[tt]);
        }
        float aj = g_A[tid], cj = g_C[tid];
        #pragma unroll
        for (int tt = 0; tt < TT; tt++)
            g_xw[(t0 + tt) * H + tid] = acc[tt] + fmaf(sRule[tt], aj, cj);
    }
}

// ---------------- K2: sequential RNN, 8-CTA cluster, paired st.async.u64 ----------------
// Thread (rr, s): row = rank*46+rr, cols [48s,48s+48) in registers (f32x2 packed).
// Per step: try_wait -> tid0 re-arm expect_tx -> BAR -> f32x2 dot -> 3 xor shfls
// -> tanh (all lanes) -> shfl_xor(8) pairs rows (2k,2k+1) -> lanes {0..7,16..23}
// each send ONE st.async.u64 (data+signal, one fabric message per row-pair).
__global__ void __cluster_dims__(CSZ, 1, 1) __launch_bounds__(384, 1)
k2_rnn(const float* __restrict__ w_hh) {
    __shared__ __align__(16) float hbuf0[HP];
    __shared__ __align__(16) float hbuf1[HP];
    __shared__ __align__(8) unsigned long long mbar[2];

    int tid = threadIdx.x;
    unsigned rank;
    asm("mov.u32 %0, %%cluster_ctarank;" : "=r"(rank));
    int s    = tid & 7;
    int rr   = tid >> 3;
    int lane = tid & 31;
    int wid  = tid >> 5;
    int row  = (int)rank * RPC + rr;
    bool active = (rr < RPC) && (row < H);

    for (int i = tid; i < HP; i += 384) { hbuf0[i] = 0.f; hbuf1[i] = 0.f; }
    unsigned mb0 = smem_u32(&mbar[0]);
    unsigned mb1 = smem_u32(&mbar[1]);
    if (tid == 0) {
        asm volatile("mbarrier.init.shared.b64 [%0], 1;" :: "r"(mb0) : "memory");
        asm volatile("mbarrier.init.shared.b64 [%0], 1;" :: "r"(mb1) : "memory");
        asm volatile("mbarrier.arrive.expect_tx.shared.b64 _, [%0], %1;"
                     :: "r"(mb0), "r"((unsigned)TXBYTES) : "memory");
        asm volatile("mbarrier.arrive.expect_tx.shared.b64 _, [%0], %1;"
                     :: "r"(mb1), "r"((unsigned)TXBYTES) : "memory");
    }

    // per-thread weight slice packed as f32x2 (zeros where masked)
    unsigned long long wp[SEG / 2];
    #pragma unroll
    for (int i = 0; i < SEG / 2; i++) {
        int c0 = s * SEG + 2 * i;
        int c1 = c0 + 1;
        float a = (active && c0 < H) ? w_hh[row * H + c0] : 0.f;
        float b = (active && c1 < H) ? w_hh[row * H + c1] : 0.f;
        asm("mov.b64 %0, {%1, %2};" : "=l"(wp[i]) : "f"(a), "f"(b));
    }

    // pair-send setup: lanes 0..7 handle pair rr=(4*wid), lanes 16..23 pair rr=(4*wid+2);
    // destination CTA = lane&7. One u64 message covers rows (rp, rp+1).
    bool is_sender = (lane < 8) || (lane >= 16 && lane < 24);
    int rrp = 4 * wid + ((lane >> 4) << 1);           // first rr of this pair
    int rowp = (int)rank * RPC + rrp;                 // first global row of pair
    bool sendok = is_sender && (rrp < RPC) && (rowp <= H - 1);
    unsigned dstp0 = 0, dstp1 = 0, rmb0 = 0, rmb1 = 0;
    if (sendok) {
        int idxp = (rowp / SEG) * SEGP + (rowp % SEG);   // even -> 8B aligned
        unsigned dcta = (unsigned)(lane & 7);
        dstp0 = mapa_u32(smem_u32(&hbuf0[idxp]), dcta);
        dstp1 = mapa_u32(smem_u32(&hbuf1[idxp]), dcta);
        rmb0  = mapa_u32(mb0, dcta);
        rmb1  = mapa_u32(mb1, dcta);
    }

    float xw_cur = active ? g_xw[row] : 0.f;
    unsigned p0 = 0, p1 = 0;

    __syncthreads();
    asm volatile("barrier.cluster.arrive.aligned;" ::: "memory");
    asm volatile("barrier.cluster.wait.aligned;" ::: "memory");

    for (int t = 0; t < T_STEPS; t++) {
        const float* cur = (t & 1) ? hbuf1 : hbuf0;

        if (t) {
            unsigned mb  = (t & 1) ? mb1 : mb0;
            unsigned par = (t & 1) ? p1 : p0;
            asm volatile(
                "{\n\t.reg .pred P1;\n\t"
                "WAITLP_%=:\n\t"
                "mbarrier.try_wait.parity.acquire.cluster.shared::cta.b64 P1, [%0], %1, 0x989680;\n\t"
                "@!P1 bra WAITLP_%=;\n\t}"
                :: "r"(mb), "r"(par) : "memory");
            if (t & 1) p1 ^= 1; else p0 ^= 1;
            if (tid == 0) {
                asm volatile("mbarrier.arrive.expect_tx.shared.b64 _, [%0], %1;"
                             :: "r"(mb), "r"((unsigned)TXBYTES) : "memory");
            }
            __syncthreads();   // stores must not pass the re-arm
        }

        float xw_nxt = 0.f;
        if (active && (t + 1 < T_STEPS)) xw_nxt = __ldg(&g_xw[(t + 1) * H + row]);

        // dot: 12 double2 smem loads (conflict-free) + 24 packed f32x2 FMAs
        const double2* h2 = reinterpret_cast<const double2*>(cur + s * SEGP);
        unsigned long long a01 = 0ull, a23 = 0ull;
        #pragma unroll
        for (int i = 0; i < 12; i++) {
            double2 hv = h2[i];
            unsigned long long h01 = __double_as_longlong(hv.x);
            unsigned long long h23 = __double_as_longlong(hv.y);
            asm("fma.rn.f32x2 %0, %1, %2, %0;" : "+l"(a01) : "l"(wp[2 * i]),     "l"(h01));
            asm("fma.rn.f32x2 %0, %1, %2, %0;" : "+l"(a23) : "l"(wp[2 * i + 1]), "l"(h23));
        }
        unsigned long long asum;
        asm("add.rn.f32x2 %0, %1, %2;" : "=l"(asum) : "l"(a01), "l"(a23));
        unsigned alo, ahi;
        asm("mov.b64 {%0, %1}, %2;" : "=r"(alo), "=r"(ahi) : "l"(asum));
        float acc = __uint_as_float(alo) + __uint_as_float(ahi);

        acc += __shfl_xor_sync(0xffffffffu, acc, 1);
        acc += __shfl_xor_sync(0xffffffffu, acc, 2);
        acc += __shfl_xor_sync(0xffffffffu, acc, 4);

        // fast tanh in every lane (inactive rows produce exactly 0)
        float x = acc + xw_cur;
        float e = __expf(x + x);
        float hval = 1.0f - __fdividef(2.0f, e + 1.0f);

        // pair rows (rr, rr^1): partner value lives 8 lanes away
        float hother = __shfl_xor_sync(0xffffffffu, hval, 8);

        if (t + 1 < T_STEPS) {
            if (sendok) {
                unsigned long long pk;
                asm("mov.b64 %0, {%1, %2};" : "=l"(pk) : "f"(hval), "f"(hother));
                unsigned dst = (t & 1) ? dstp0 : dstp1;   // h_{t+1} -> buf[(t+1)&1]
                unsigned rmb = (t & 1) ? rmb0 : rmb1;
                asm volatile(
                    "st.async.shared::cluster.mbarrier::complete_tx::bytes.u64 [%0], %1, [%2];"
                    :: "r"(dst), "l"(pk), "r"(rmb) : "memory");
            }
        }
        if (active && s == 0) g_hs[t * H + row] = hval;
        xw_cur = xw_nxt;
    }
    asm volatile("barrier.cluster.arrive.aligned;" ::: "memory");
    asm volatile("barrier.cluster.wait.aligned;" ::: "memory");
}

// ---------------- K3: outcome_pre + hs copy-out ----------------
__global__ void k3_outcome(const float* __restrict__ w_fc, const float* __restrict__ b_fc,
                           float* __restrict__ pre) {
    __shared__ float swfc[H];
    for (int i = threadIdx.x; i < H; i += blockDim.x) swfc[i] = w_fc[i];
    __syncthreads();
    int lane = threadIdx.x & 31;
    int wid  = threadIdx.x >> 5;
    int wpb  = blockDim.x >> 5;
    float bf = b_fc[0];
    for (int t = blockIdx.x * wpb + wid; t < T_STEPS; t += gridDim.x * wpb) {
        const float* hrow = g_hs + t * H;
        float acc = 0.f;
        for (int i = lane; i < H; i += 32) acc = fmaf(hrow[i], swfc[i], acc);
        #pragma unroll
        for (int o = 16; o > 0; o >>= 1) acc += __shfl_xor_sync(0xffffffffu, acc, o);
        if (lane == 0) pre[t] = acc + bf;
    }
}

__global__ void k3_copy(float* __restrict__ dst) {
    const float4* src = reinterpret_cast<const float4*>(g_hs);
    float4* d = reinterpret_cast<float4*>(dst);
    int n4 = T_STEPS * H / 4;
    for (int i = blockIdx.x * blockDim.x + threadIdx.x; i < n4; i += gridDim.x * blockDim.x)
        d[i] = src[i];
}

// ---------------- launch ----------------
extern "C" void kernel_launch(void* const* d_in, const int* in_sizes, int n_in,
                              void* d_out, int out_size) {
    const float* angle  = (const float*)d_in[0];
    const float* rule   = (const float*)d_in[1];
    const float* w_rule = (const float*)d_in[2];
    const float* b_rule = (const float*)d_in[3];
    const float* w_ih   = (const float*)d_in[4];
    const float* w_hh   = (const float*)d_in[5];
    const float* b_ih   = (const float*)d_in[6];
    const float* b_hh   = (const float*)d_in[7];
    const float* w_fc   = (const float*)d_in[8];
    const float* b_fc   = (const float*)d_in[9];
    float* out = (float*)d_out;

    k0_prep<<<(H + 255) / 256, 256>>>(w_rule, b_rule, w_ih, b_ih, b_hh);
    k0_transpose<<<(H * H + 255) / 256, 256>>>(w_ih);
    k1_xw<<<T_STEPS / TT, 384>>>(angle, rule);
    k2_rnn<<<CSZ, 384>>>(w_hh);

    float* pre = nullptr;
    float* hs_dst = nullptr;
    if (out_size == T_STEPS * (H + 1)) { pre = out; hs_dst = out + T_STEPS; }
    else if (out_size == T_STEPS * H)  { hs_dst = out; }
    else if (out_size == T_STEPS)      { pre = out; }
    else {
        pre = out;
        if (out_size >= T_STEPS * (H + 1)) hs_dst = out + (out_size - T_STEPS * H);
    }
    if (hs_dst) k3_copy<<<1024, 256>>>(hs_dst);
    if (pre)    k3_outcome<<<256, 256>>>(w_fc, b_fc, pre);
}

// round 7
// speedup vs baseline: 1.0679x; 1.0679x over previous
#include <cuda_runtime.h>

#define T_STEPS 16384
#define H 361

#define SEG 48
#define SEGP 52
#define NSEG 8
#define HP (NSEG * SEGP)   /* 416 */
#define RPC 46
#define CSZ 8
#define TXBYTES (H * 4)    /* 1444 bytes per consumer per step */

#define KAPPA_F 32.84045313f
#define NORMF   2.2773755f
#define DEG2RAD 0.017453292519943295f

// ---------------- device scratch ----------------
__device__ float g_xw[T_STEPS * H];
__device__ float g_W2T[H * 368];
__device__ float g_A[H];
__device__ float g_C[H];
__device__ float g_hs[T_STEPS * H];

__device__ __forceinline__ unsigned smem_u32(const void* p) {
    return (unsigned)__cvta_generic_to_shared(p);
}
__device__ __forceinline__ unsigned mapa_u32(unsigned addr, unsigned rank) {
    unsigned r;
    asm("mapa.shared::cluster.u32 %0, %1, %2;" : "=r"(r) : "r"(addr), "r"(rank));
    return r;
}

// ---------------- K0: collapse rule projection + biases ----------------
__global__ void k0_prep(const float* __restrict__ w_rule, const float* __restrict__ b_rule,
                        const float* __restrict__ w_ih, const float* __restrict__ b_ih,
                        const float* __restrict__ b_hh) {
    int j = blockIdx.x * blockDim.x + threadIdx.x;
    if (j >= H) return;
    float a = 0.f, c = 0.f;
    const float* wr = w_ih + j * 489;
    for (int k = 0; k < 128; k++) {
        float w = wr[k];
        a = fmaf(w_rule[k], w, a);
        c = fmaf(b_rule[k], w, c);
    }
    g_A[j] = a;
    g_C[j] = c + b_ih[j] + b_hh[j];
}

__global__ void k0_transpose(const float* __restrict__ w_ih) {
    int idx = blockIdx.x * blockDim.x + threadIdx.x;
    if (idx >= H * H) return;
    int j = idx / H;
    int g = idx - j * H;
    g_W2T[g * 368 + j] = w_ih[j * 489 + 128 + g];
}

// ---------------- K1: xw precompute ----------------
#define TT 16
__global__ __launch_bounds__(384) void k1_xw(const float* __restrict__ angle,
                                             const float* __restrict__ rule) {
    __shared__ float sE[TT][H];
    __shared__ float sAng[TT], sRule[TT];
    int tid = threadIdx.x;
    int t0 = blockIdx.x * TT;
    if (tid < TT) {
        sAng[tid]  = angle[t0 + tid] * DEG2RAD;
        sRule[tid] = rule[t0 + tid];
    }
    __syncthreads();
    if (tid < H) {
        float gr = (float)tid * DEG2RAD;
        #pragma unroll
        for (int tt = 0; tt < TT; tt++) {
            float th = gr - sAng[tt];
            sE[tt][tid] = __expf(KAPPA_F * (cosf(th) - 1.0f)) * NORMF;
        }
    }
    __syncthreads();
    if (tid < H) {
        float acc[TT];
        #pragma unroll
        for (int tt = 0; tt < TT; tt++) acc[tt] = 0.f;
        #pragma unroll 2
        for (int g = 0; g < H; g++) {
            float w = g_W2T[g * 368 + tid];
            #pragma unroll
            for (int tt = 0; tt < TT; tt++) acc[tt] = fmaf(sE[tt][g], w, acc[tt]);
        }
        float aj = g_A[tid], cj = g_C[tid];
        #pragma unroll
        for (int tt = 0; tt < TT; tt++)
            g_xw[(t0 + tt) * H + tid] = acc[tt] + fmaf(sRule[tt], aj, cj);
    }
}

// ---------------- K2: sequential RNN, 8-CTA cluster, st.async fused data+signal ----------------
// R7: 3-shfl group reduce (redux.f32 unsupported on sm_103); no __syncthreads
// after re-arm (tx-count may legally go negative); 4 FMA accumulator chains.
__global__ void __cluster_dims__(CSZ, 1, 1) __launch_bounds__(384, 1)
k2_rnn(const float* __restrict__ w_hh) {
    __shared__ __align__(16) float hbuf0[HP];
    __shared__ __align__(16) float hbuf1[HP];
    __shared__ __align__(8) unsigned long long mbar[2];

    int tid = threadIdx.x;
    unsigned rank;
    asm("mov.u32 %0, %%cluster_ctarank;" : "=r"(rank));
    int s    = tid & 7;
    int rr   = tid >> 3;
    int row  = (int)rank * RPC + rr;
    bool active = (rr < RPC) && (row < H);

    for (int i = tid; i < HP; i += 384) { hbuf0[i] = 0.f; hbuf1[i] = 0.f; }
    unsigned mb0 = smem_u32(&mbar[0]);
    unsigned mb1 = smem_u32(&mbar[1]);
    if (tid == 0) {
        asm volatile("mbarrier.init.shared.b64 [%0], 1;" :: "r"(mb0) : "memory");
        asm volatile("mbarrier.init.shared.b64 [%0], 1;" :: "r"(mb1) : "memory");
        asm volatile("mbarrier.arrive.expect_tx.shared.b64 _, [%0], %1;"
                     :: "r"(mb0), "r"((unsigned)TXBYTES) : "memory");
        asm volatile("mbarrier.arrive.expect_tx.shared.b64 _, [%0], %1;"
                     :: "r"(mb1), "r"((unsigned)TXBYTES) : "memory");
    }

    // per-thread weight slice packed as f32x2 (zeros where masked)
    unsigned long long wp[SEG / 2];
    #pragma unroll
    for (int i = 0; i < SEG / 2; i++) {
        int c0 = s * SEG + 2 * i;
        int c1 = c0 + 1;
        float a = (active && c0 < H) ? w_hh[row * H + c0] : 0.f;
        float b = (active && c1 < H) ? w_hh[row * H + c1] : 0.f;
        asm("mov.b64 %0, {%1, %2};" : "=l"(wp[i]) : "f"(a), "f"(b));
    }

    // remote destinations for this thread's row value -> CTA s (data + mbar)
    int idx_store = (row / SEG) * SEGP + (row % SEG);
    unsigned dst0 = 0, dst1 = 0, rmb0 = 0, rmb1 = 0;
    if (active) {
        dst0 = mapa_u32(smem_u32(&hbuf0[idx_store]), (unsigned)s);
        dst1 = mapa_u32(smem_u32(&hbuf1[idx_store]), (unsigned)s);
        rmb0 = mapa_u32(mb0, (unsigned)s);
        rmb1 = mapa_u32(mb1, (unsigned)s);
    }

    float xw_cur = active ? g_xw[row] : 0.f;
    unsigned p0 = 0, p1 = 0;

    __syncthreads();
    asm volatile("barrier.cluster.arrive.aligned;" ::: "memory");
    asm volatile("barrier.cluster.wait.aligned;" ::: "memory");

    for (int t = 0; t < T_STEPS; t++) {
        const float* cur = (t & 1) ? hbuf1 : hbuf0;

        if (t) {
            unsigned mb  = (t & 1) ? mb1 : mb0;
            unsigned par = (t & 1) ? p1 : p0;
            asm volatile(
                "{\n\t.reg .pred P1;\n\t"
                "WAITLP_%=:\n\t"
                "mbarrier.try_wait.parity.acquire.cluster.shared::cta.b64 P1, [%0], %1, 0x989680;\n\t"
                "@!P1 bra WAITLP_%=;\n\t}"
                :: "r"(mb), "r"(par) : "memory");
            if (t & 1) p1 ^= 1; else p0 ^= 1;
            // re-arm for step t+2; no fence needed (complete_tx-before-expect_tx
            // is legal; pending arrive-count prevents early phase completion)
            if (tid == 0) {
                asm volatile("mbarrier.arrive.expect_tx.shared.b64 _, [%0], %1;"
                             :: "r"(mb), "r"((unsigned)TXBYTES) : "memory");
            }
        }

        float xw_nxt = 0.f;
        if (active && (t + 1 < T_STEPS)) xw_nxt = __ldg(&g_xw[(t + 1) * H + row]);

        // dot: 12 double2 smem loads (conflict-free) + 24 packed f32x2 FMAs,
        // 4 accumulator chains (dep depth 6)
        const double2* h2 = reinterpret_cast<const double2*>(cur + s * SEGP);
        unsigned long long a01 = 0ull, a23 = 0ull, a45 = 0ull, a67 = 0ull;
        #pragma unroll
        for (int i = 0; i < 6; i++) {
            double2 hva = h2[2 * i];
            double2 hvb = h2[2 * i + 1];
            unsigned long long h01 = __double_as_longlong(hva.x);
            unsigned long long h23 = __double_as_longlong(hva.y);
            unsigned long long h45 = __double_as_longlong(hvb.x);
            unsigned long long h67 = __double_as_longlong(hvb.y);
            asm("fma.rn.f32x2 %0, %1, %2, %0;" : "+l"(a01) : "l"(wp[4 * i]),     "l"(h01));
            asm("fma.rn.f32x2 %0, %1, %2, %0;" : "+l"(a23) : "l"(wp[4 * i + 1]), "l"(h23));
            asm("fma.rn.f32x2 %0, %1, %2, %0;" : "+l"(a45) : "l"(wp[4 * i + 2]), "l"(h45));
            asm("fma.rn.f32x2 %0, %1, %2, %0;" : "+l"(a67) : "l"(wp[4 * i + 3]), "l"(h67));
        }
        unsigned long long s0, s1, ssum;
        asm("add.rn.f32x2 %0, %1, %2;" : "=l"(s0) : "l"(a01), "l"(a23));
        asm("add.rn.f32x2 %0, %1, %2;" : "=l"(s1) : "l"(a45), "l"(a67));
        asm("add.rn.f32x2 %0, %1, %2;" : "=l"(ssum) : "l"(s0), "l"(s1));
        unsigned alo, ahi;
        asm("mov.b64 {%0, %1}, %2;" : "=r"(alo), "=r"(ahi) : "l"(ssum));
        float acc = __uint_as_float(alo) + __uint_as_float(ahi);

        // 8-lane group reduce (proven path)
        acc += __shfl_xor_sync(0xffffffffu, acc, 1);
        acc += __shfl_xor_sync(0xffffffffu, acc, 2);
        acc += __shfl_xor_sync(0xffffffffu, acc, 4);

        // fast tanh in every lane of the row group
        float x = acc + xw_cur;
        float e = __expf(x + x);
        float hval = 1.0f - __fdividef(2.0f, e + 1.0f);

        if (active && (t + 1 < T_STEPS)) {
            unsigned dst = (t & 1) ? dst0 : dst1;   // h_{t+1} -> buf[(t+1)&1]
            unsigned rmb = (t & 1) ? rmb0 : rmb1;
            asm volatile(
                "st.async.shared::cluster.mbarrier::complete_tx::bytes.u32 [%0], %1, [%2];"
                :: "r"(dst), "r"(__float_as_uint(hval)), "r"(rmb) : "memory");
        }
        if (active && s == 0) g_hs[t * H + row] = hval;
        xw_cur = xw_nxt;
    }
    asm volatile("barrier.cluster.arrive.aligned;" ::: "memory");
    asm volatile("barrier.cluster.wait.aligned;" ::: "memory");
}

// ---------------- K3: outcome_pre + hs copy-out ----------------
__global__ void k3_outcome(const float* __restrict__ w_fc, const float* __restrict__ b_fc,
                           float* __restrict__ pre) {
    __shared__ float swfc[H];
    for (int i = threadIdx.x; i < H; i += blockDim.x) swfc[i] = w_fc[i];
    __syncthreads();
    int lane = threadIdx.x & 31;
    int wid  = threadIdx.x >> 5;
    int wpb  = blockDim.x >> 5;
    float bf = b_fc[0];
    for (int t = blockIdx.x * wpb + wid; t < T_STEPS; t += gridDim.x * wpb) {
        const float* hrow = g_hs + t * H;
        float acc = 0.f;
        for (int i = lane; i < H; i += 32) acc = fmaf(hrow[i], swfc[i], acc);
        #pragma unroll
        for (int o = 16; o > 0; o >>= 1) acc += __shfl_xor_sync(0xffffffffu, acc, o);
        if (lane == 0) pre[t] = acc + bf;
    }
}

__global__ void k3_copy(float* __restrict__ dst) {
    const float4* src = reinterpret_cast<const float4*>(g_hs);
    float4* d = reinterpret_cast<float4*>(dst);
    int n4 = T_STEPS * H / 4;
    for (int i = blockIdx.x * blockDim.x + threadIdx.x; i < n4; i += gridDim.x * blockDim.x)
        d[i] = src[i];
}

// ---------------- launch ----------------
extern "C" void kernel_launch(void* const* d_in, const int* in_sizes, int n_in,
                              void* d_out, int out_size) {
    const float* angle  = (const float*)d_in[0];
    const float* rule   = (const float*)d_in[1];
    const float* w_rule = (const float*)d_in[2];
    const float* b_rule = (const float*)d_in[3];
    const float* w_ih   = (const float*)d_in[4];
    const float* w_hh   = (const float*)d_in[5];
    const float* b_ih   = (const float*)d_in[6];
    const float* b_hh   = (const float*)d_in[7];
    const float* w_fc   = (const float*)d_in[8];
    const float* b_fc   = (const float*)d_in[9];
    float* out = (float*)d_out;

    k0_prep<<<(H + 255) / 256, 256>>>(w_rule, b_rule, w_ih, b_ih, b_hh);
    k0_transpose<<<(H * H + 255) / 256, 256>>>(w_ih);
    k1_xw<<<T_STEPS / TT, 384>>>(angle, rule);
    k2_rnn<<<CSZ, 384>>>(w_hh);

    float* pre = nullptr;
    float* hs_dst = nullptr;
    if (out_size == T_STEPS * (H + 1)) { pre = out; hs_dst = out + T_STEPS; }
    else if (out_size == T_STEPS * H)  { hs_dst = out; }
    else if (out_size == T_STEPS)      { pre = out; }
    else {
        pre = out;
        if (out_size >= T_STEPS * (H + 1)) hs_dst = out + (out_size - T_STEPS * H);
    }
    if (hs_dst) k3_copy<<<1024, 256>>>(hs_dst);
    if (pre)    k3_outcome<<<256, 256>>>(w_fc, b_fc, pre);
}